// round 5
// baseline (speedup 1.0000x reference)
#include <cuda_runtime.h>
#include <stdint.h>

// AE_spikes via mma.sync s8 tensor cores. Layers = GEMM over rows (t,b).
// Weights as 3 s8 limbs base 254 (near-exact); per-limb int32 accumulators
// persist across K panels; limbs combined once. Fire-and-reset scan fused.
// NEW: ldmatrix.x4 fragment loads (4x fewer shared-load issues) and
// flag-and-repair: membranes within EPS of threshold are recomputed with
// bit-exact reference fp32 semantics (ascending-k adds) for rel_err ~ 0.

#define BATCH  16384
#define TSTEPS 16
#define KP1    896        // 784 padded to 7*128
#define EPS    1e-4f
#define FCAP   262144

// ---------------- scratch ----------------
__device__ uint16_t g_M0[BATCH * KP1];
__device__ uint16_t g_M1[BATCH * 128];
__device__ uint16_t g_M2[BATCH * 128];
__device__ uint16_t g_M3[BATCH * 128];
__device__ int8_t   g_Q1[3 * 128 * KP1];
__device__ int8_t   g_Q2[3 * 128 * 128];
__device__ int8_t   g_Q3[3 * 128 * 128];
__device__ int8_t   g_Q4[3 * 784 * 128];
__device__ float    g_S1[128], g_S2[128], g_S3[128], g_S4[784];
__device__ int      g_cnt[4];
__device__ uint32_t g_flag[4][FCAP];

// ---------------- helpers ----------------
__device__ __forceinline__ uint32_t smem_u32(const void* p) {
    uint32_t a;
    asm("{ .reg .u64 t; cvta.to.shared.u64 t, %1; cvt.u32.u64 %0, t; }"
        : "=r"(a) : "l"(p));
    return a;
}
__device__ __forceinline__ void mma8(int* d, const uint32_t* a, uint32_t b0, uint32_t b1) {
    asm volatile(
        "mma.sync.aligned.m16n8k32.row.col.s32.s8.s8.s32 "
        "{%0,%1,%2,%3}, {%4,%5,%6,%7}, {%8,%9}, {%0,%1,%2,%3};"
        : "+r"(d[0]), "+r"(d[1]), "+r"(d[2]), "+r"(d[3])
        : "r"(a[0]), "r"(a[1]), "r"(a[2]), "r"(a[3]), "r"(b0), "r"(b1));
}
__device__ __forceinline__ void ldsm4(uint32_t& r0, uint32_t& r1, uint32_t& r2,
                                      uint32_t& r3, uint32_t addr) {
    asm volatile("ldmatrix.sync.aligned.m8n8.x4.shared.b16 {%0,%1,%2,%3}, [%4];"
                 : "=r"(r0), "=r"(r1), "=r"(r2), "=r"(r3) : "r"(addr));
}
__device__ __forceinline__ void cpa16(uint32_t dst, const void* src, uint32_t ssz) {
    asm volatile("cp.async.cg.shared.global [%0], [%1], 16, %2;"
                 :: "r"(dst), "l"(src), "r"(ssz));
}

__global__ void zero_cnt_kernel() { if (threadIdx.x < 4) g_cnt[threadIdx.x] = 0; }

// ---------------- encoder (bit-exact) ----------------
__global__ void __launch_bounds__(256) enc_kernel(const float* __restrict__ f) {
    int idx = blockIdx.x * blockDim.x + threadIdx.x;
    if (idx >= BATCH * KP1) return;
    int b = idx / KP1, i = idx - b * KP1;
    unsigned m = 0;
    if (i < 784) {
        float x = f[b * 784 + i], v = 0.0f;
#pragma unroll
        for (int t = 0; t < TSTEPS; t++) {
            v += x;
            if (v >= 1.0f) { m |= (1u << t); v -= 1.0f; }
        }
    }
    g_M0[idx] = (uint16_t)m;
}

// ---------------- weight 3-limb s8 split, base 254 ----------------
__global__ void __launch_bounds__(32) wsplit(const float* __restrict__ W,
                                             int8_t* __restrict__ Q,
                                             float* __restrict__ S,
                                             int N, int K, int KP)
{
    int j = blockIdx.x, lane = threadIdx.x;
    const float* w = W + (size_t)j * K;
    float m = 0.0f;
    for (int k = lane; k < K; k += 32) m = fmaxf(m, fabsf(w[k]));
#pragma unroll
    for (int o = 16; o; o >>= 1) m = fmaxf(m, __shfl_xor_sync(~0u, m, o));
    float s0 = (m > 0.0f) ? m / 127.0f : 1.0f;
    if (lane == 0) S[j] = s0;
    double s0d = (double)s0;
    for (int k = lane; k < KP; k += 32) {
        double q0 = 0.0, q1 = 0.0, q2 = 0.0;
        if (k < K) {
            double wd = (double)w[k];
            q0 = fmin(fmax(rint(wd / s0d), -127.0), 127.0);
            double r1 = wd - q0 * s0d;
            q1 = fmin(fmax(rint(r1 * 254.0 / s0d), -127.0), 127.0);
            double r2 = r1 - q1 * s0d / 254.0;
            q2 = fmin(fmax(rint(r2 * 64516.0 / s0d), -127.0), 127.0);
        }
        size_t base = (size_t)j * KP + k, lstr = (size_t)N * KP;
        Q[base]            = (int8_t)(int)q0;
        Q[base + lstr]     = (int8_t)(int)q1;
        Q[base + 2 * lstr] = (int8_t)(int)q2;
    }
}

// ---------------- fused s8-GEMM + spiking scan + flagging ----------------
// grid: (BATCH/8, ceil(NOUT/64)); 256 threads. CTA M=128 (8b x 16t) x N=64.
template <int KP, int NOUT, bool IS_LAST, int LID>
__global__ void __launch_bounds__(256, 2) gemm_spike(
    const uint16_t* __restrict__ Min, const int8_t* __restrict__ Wq,
    const float* __restrict__ Sc, const float* __restrict__ bias,
    uint16_t* __restrict__ Mout, float* __restrict__ Out)
{
    extern __shared__ __align__(16) char sm[];
    constexpr int NPAN   = KP / 128;
    constexpr int MSK_B  = 8 * KP * 2;
    constexpr int OFF_A  = MSK_B;                 // 128 rows x pitch 144 s8
    constexpr int OFF_B  = OFF_A + 128 * 144;     // 2 bufs x 3 limbs x 64 x 144
    constexpr int OFF_SC = OFF_B + 2 * 3 * 64 * 144;
    constexpr int OFF_C  = OFF_A;                 // scan buf reuses A+B region
    constexpr int BBUF   = 3 * 64 * 144;

    const uint32_t sbase = smem_u32(sm);
    const int tid  = threadIdx.x;
    const int lane = tid & 31, wm = tid >> 5;
    const int g = lane >> 2, tg = lane & 3;
    const int b0 = blockIdx.x * 8;
    const int n0 = blockIdx.y * 64;

    {
        const uint4* msrc = (const uint4*)(Min + (size_t)b0 * KP);
        uint4* mdst = (uint4*)sm;
        for (int u = tid; u < MSK_B / 16; u += 256) mdst[u] = msrc[u];
    }
    if (tid < 64) {
        int j = n0 + tid;
        float s = (j < NOUT) ? Sc[j] : 0.0f;
        ((float*)(sm + OFF_SC))[tid]       = s;
        ((float*)(sm + OFF_SC))[64 + tid]  = s * (1.0f / 64516.0f);
        ((float*)(sm + OFF_SC))[128 + tid] = (j < NOUT) ? bias[j] : 0.0f;
    }
    auto loadB = [&](int p, int buf) {
        const int bk = p * 128;
        for (int v = tid; v < 1536; v += 256) {
            int l = v >> 9, rem = v & 511, r = rem >> 3, cs = rem & 7;
            int row = n0 + r;
            uint32_t ssz = (row < NOUT) ? 16u : 0u;
            int rc = row < NOUT ? row : 0;
            const int8_t* src = Wq + ((size_t)l * NOUT + rc) * KP + bk + cs * 16;
            cpa16(sbase + OFF_B + buf * BBUF + l * 9216 + r * 144 + cs * 16, src, ssz);
        }
        asm volatile("cp.async.commit_group;");
    };
    loadB(0, 0);
    __syncthreads();

    int D0[8][4], D1[8][4], D2[8][4];
#pragma unroll
    for (int ni = 0; ni < 8; ni++)
#pragma unroll
        for (int r = 0; r < 4; r++) { D0[ni][r] = 0; D1[ni][r] = 0; D2[ni][r] = 0; }

    // ldmatrix lane address bases (per-thread)
    const int mi = lane >> 3, r8 = lane & 7;
    const uint32_t a_lbase = sbase + OFF_A +
        (uint32_t)((wm * 16 + r8 + (mi & 1) * 8) * 144 + (mi >> 1) * 16);
    const uint32_t b_lbase = sbase + OFF_B +
        (uint32_t)((((mi >> 1) & 1) * 8 + r8) * 144 + (mi & 1) * 16);

#pragma unroll 1
    for (int p = 0; p < NPAN; p++) {
        const int buf = p & 1;
        // expand A panel: bitmask bit t -> s8 rows
        {
            const uint64_t* m64 = (const uint64_t*)sm;
            int bl = tid >> 5, kq = tid & 31;
            uint64_t mv = m64[bl * (KP / 4) + p * 32 + kq];
            uint32_t lo = (uint32_t)mv, hi = (uint32_t)(mv >> 32);
            char* arow = sm + OFF_A + (bl * 16) * 144 + kq * 4;
#pragma unroll
            for (int t = 0; t < 16; t++) {
                uint32_t xl = (lo >> t) & 0x00010001u; xl |= xl >> 15;
                uint32_t xh = (hi >> t) & 0x00010001u; xh |= xh >> 15;
                uint32_t nib = (xl & 3u) | ((xh & 3u) << 2);
                *(uint32_t*)(arow + t * 144) = (nib * 0x00204081u) & 0x01010101u;
            }
        }
        if (p + 1 < NPAN) {
            loadB(p + 1, buf ^ 1);
            asm volatile("cp.async.wait_group 1;");
        } else {
            asm volatile("cp.async.wait_group 0;");
        }
        __syncthreads();

        const uint32_t bb0 = b_lbase + buf * BBUF;
#pragma unroll
        for (int ch = 0; ch < 4; ch++) {
            uint32_t afr[4];
            ldsm4(afr[0], afr[1], afr[2], afr[3], a_lbase + ch * 32);
#pragma unroll
            for (int np = 0; np < 4; np++) {
                const uint32_t bnp = bb0 + np * 2304 + ch * 32;
                uint32_t q0, q1, q2, q3;
                ldsm4(q0, q1, q2, q3, bnp);
                mma8(D0[2 * np], afr, q0, q1);
                mma8(D0[2 * np + 1], afr, q2, q3);
                ldsm4(q0, q1, q2, q3, bnp + 9216);
                mma8(D1[2 * np], afr, q0, q1);
                mma8(D1[2 * np + 1], afr, q2, q3);
                ldsm4(q0, q1, q2, q3, bnp + 18432);
                mma8(D2[2 * np], afr, q0, q1);
                mma8(D2[2 * np + 1], afr, q2, q3);
            }
        }
        __syncthreads();
    }

    // combine limbs and store to scan buffer
    float* cs = (float*)(sm + OFF_C);
    const float* s0a  = (const float*)(sm + OFF_SC);
    const float* c12a = (const float*)(sm + OFF_SC) + 64;
#pragma unroll
    for (int ni = 0; ni < 8; ni++)
#pragma unroll
        for (int r = 0; r < 4; r++) {
            int row = wm * 16 + g + (r >> 1) * 8;
            int col = ni * 8 + tg * 2 + (r & 1);
            int d12 = D1[ni][r] * 254 + D2[ni][r];
            cs[row * 64 + col] = s0a[col] * (float)D0[ni][r] + c12a[col] * (float)d12;
        }
    __syncthreads();

    // sequential t-scan + near-threshold flagging
    const float* ba = (const float*)(sm + OFF_SC) + 128;
#pragma unroll
    for (int u = 0; u < 2; u++) {
        int pr = tid + 256 * u;
        int j = pr & 63, bl = pr >> 6;
        float bj = ba[j];
        const float* colp = cs + bl * 16 * 64 + j;
        float v = 0.0f;
        uint32_t msk = 0;
        bool flag = false;
#pragma unroll
        for (int t = 0; t < 16; t++) {
            v = (v + colp[t * 64]) + bj;
            flag |= (fabsf(v - 1.0f) < EPS);
            if (v >= 1.0f) { msk |= (1u << t); v -= 1.0f; }
        }
        int jj = n0 + j;
        if (jj < NOUT) {
            int b = b0 + bl;
            if (IS_LAST)
                Out[(size_t)b * NOUT + jj] = (float)__popc(msk) * 0.0625f;
            else
                Mout[(size_t)b * NOUT + jj] = (uint16_t)msk;
            if (flag) {
                int s = atomicAdd(&g_cnt[LID], 1);
                if (s < FCAP) g_flag[LID][s] = ((uint32_t)b << 10) | (uint32_t)jj;
            }
        }
    }
}

// ---------------- repair: recompute flagged chains with reference bits -----
template <int KP, int K, int NOUT, bool IS_LAST, int LID>
__global__ void __launch_bounds__(256) repair_kernel(
    const uint16_t* __restrict__ Min, const float* __restrict__ W,
    const float* __restrict__ bias, uint16_t* __restrict__ Mout,
    float* __restrict__ Out)
{
    int n = g_cnt[LID];
    if (n > FCAP) n = FCAP;
    for (int s = blockIdx.x * blockDim.x + threadIdx.x; s < n;
         s += gridDim.x * blockDim.x) {
        uint32_t pk = g_flag[LID][s];
        int b = (int)(pk >> 10), j = (int)(pk & 1023u);
        const uint16_t* mrow = Min + (size_t)b * KP;
        const float* wr = W + (size_t)j * K;
        float acc[TSTEPS];
#pragma unroll
        for (int t = 0; t < TSTEPS; t++) acc[t] = 0.0f;
        for (int i = 0; i < K; i++) {
            unsigned m = mrow[i];
            if (!m) continue;          // adding 0.0f*w terms is a bit-exact no-op
            float w = wr[i];
#pragma unroll
            for (int t = 0; t < TSTEPS; t++)
                if (m & (1u << t)) acc[t] += w;
        }
        float bj = bias[j], v = 0.0f;
        uint32_t msk = 0;
#pragma unroll
        for (int t = 0; t < TSTEPS; t++) {
            v = (v + acc[t]) + bj;
            if (v >= 1.0f) { msk |= (1u << t); v -= 1.0f; }
        }
        if (IS_LAST)
            Out[(size_t)b * NOUT + j] = (float)__popc(msk) * 0.0625f;
        else
            Mout[(size_t)b * NOUT + j] = (uint16_t)msk;
    }
}

// ---------------------------------------------------------------------------
extern "C" void kernel_launch(void* const* d_in, const int* in_sizes, int n_in,
                              void* d_out, int out_size)
{
    const float* features = (const float*)d_in[0];
    const float* W1 = (const float*)d_in[1];
    const float* b1 = (const float*)d_in[2];
    const float* W2 = (const float*)d_in[3];
    const float* b2 = (const float*)d_in[4];
    const float* W3 = (const float*)d_in[5];
    const float* b3 = (const float*)d_in[6];
    const float* W4 = (const float*)d_in[7];
    const float* b4 = (const float*)d_in[8];
    float* out = (float*)d_out;

    uint16_t *m0, *m1, *m2, *m3;
    int8_t *q1, *q2, *q3, *q4;
    float *s1, *s2, *s3, *s4;
    cudaGetSymbolAddress((void**)&m0, g_M0);
    cudaGetSymbolAddress((void**)&m1, g_M1);
    cudaGetSymbolAddress((void**)&m2, g_M2);
    cudaGetSymbolAddress((void**)&m3, g_M3);
    cudaGetSymbolAddress((void**)&q1, g_Q1);
    cudaGetSymbolAddress((void**)&q2, g_Q2);
    cudaGetSymbolAddress((void**)&q3, g_Q3);
    cudaGetSymbolAddress((void**)&q4, g_Q4);
    cudaGetSymbolAddress((void**)&s1, g_S1);
    cudaGetSymbolAddress((void**)&s2, g_S2);
    cudaGetSymbolAddress((void**)&s3, g_S3);
    cudaGetSymbolAddress((void**)&s4, g_S4);

    zero_cnt_kernel<<<1, 32>>>();
    enc_kernel<<<(BATCH * KP1 + 255) / 256, 256>>>(features);
    wsplit<<<128, 32>>>(W1, q1, s1, 128, 784, KP1);
    wsplit<<<128, 32>>>(W2, q2, s2, 128, 128, 128);
    wsplit<<<128, 32>>>(W3, q3, s3, 128, 128, 128);
    wsplit<<<784, 32>>>(W4, q4, s4, 784, 128, 128);

    constexpr int SM_L1 = 8 * KP1 * 2 + 128 * 144 + 2 * 3 * 64 * 144 + 768;
    constexpr int SM_H  = 8 * 128 * 2 + 128 * 144 + 2 * 3 * 64 * 144 + 768;

    cudaFuncSetAttribute(gemm_spike<KP1, 128, false, 0>,
                         cudaFuncAttributeMaxDynamicSharedMemorySize, SM_L1);
    cudaFuncSetAttribute(gemm_spike<128, 128, false, 1>,
                         cudaFuncAttributeMaxDynamicSharedMemorySize, SM_H);
    cudaFuncSetAttribute(gemm_spike<128, 128, false, 2>,
                         cudaFuncAttributeMaxDynamicSharedMemorySize, SM_H);
    cudaFuncSetAttribute(gemm_spike<128, 784, true, 3>,
                         cudaFuncAttributeMaxDynamicSharedMemorySize, SM_H);

    gemm_spike<KP1, 128, false, 0>
        <<<dim3(BATCH / 8, 2), 256, SM_L1>>>(m0, q1, s1, b1, m1, nullptr);
    repair_kernel<KP1, 784, 128, false, 0><<<128, 256>>>(m0, W1, b1, m1, nullptr);

    gemm_spike<128, 128, false, 1>
        <<<dim3(BATCH / 8, 2), 256, SM_H>>>(m1, q2, s2, b2, m2, nullptr);
    repair_kernel<128, 128, 128, false, 1><<<128, 256>>>(m1, W2, b2, m2, nullptr);

    gemm_spike<128, 128, false, 2>
        <<<dim3(BATCH / 8, 2), 256, SM_H>>>(m2, q3, s3, b3, m3, nullptr);
    repair_kernel<128, 128, 128, false, 2><<<128, 256>>>(m2, W3, b3, m3, nullptr);

    gemm_spike<128, 784, true, 3>
        <<<dim3(BATCH / 8, 13), 256, SM_H>>>(m3, q4, s4, b4, nullptr, out);
    repair_kernel<128, 128, 784, true, 3><<<128, 256>>>(m3, W4, b4, nullptr, out);
}

// round 7
// speedup vs baseline: 1.1145x; 1.1145x over previous
#include <cuda_runtime.h>
#include <stdint.h>

// AE_spikes via mma.sync s8 tensor cores. Layers = GEMM over rows (t,b).
// Weights as 2 s8 limbs base 254 (residual <= s0/508); per-limb int32
// accumulators persist across K panels (exact); combined once at the end.
// Fire-and-reset scan fused in epilogue. Membranes within EPS of threshold
// are flagged and repaired with bit-exact reference fp32 semantics
// (ascending-k adds) -> rel_err 0 with 2/3 of the 3-limb MMA cost.

#define BATCH  16384
#define TSTEPS 16
#define KP1    896        // 784 padded to 7*128
#define EPS    1e-3f
#define FCAP   1048576

// ---------------- scratch ----------------
__device__ uint16_t g_M0[BATCH * KP1];
__device__ uint16_t g_M1[BATCH * 128];
__device__ uint16_t g_M2[BATCH * 128];
__device__ uint16_t g_M3[BATCH * 128];
__device__ int8_t   g_Q1[2 * 128 * KP1];
__device__ int8_t   g_Q2[2 * 128 * 128];
__device__ int8_t   g_Q3[2 * 128 * 128];
__device__ int8_t   g_Q4[2 * 784 * 128];
__device__ float    g_S1[128], g_S2[128], g_S3[128], g_S4[784];
__device__ int      g_cnt[4];
__device__ uint32_t g_flag[4][FCAP];

// ---------------- helpers ----------------
__device__ __forceinline__ uint32_t smem_u32(const void* p) {
    uint32_t a;
    asm("{ .reg .u64 t; cvta.to.shared.u64 t, %1; cvt.u32.u64 %0, t; }"
        : "=r"(a) : "l"(p));
    return a;
}
__device__ __forceinline__ void mma8(int* d, const uint32_t* a, uint32_t b0, uint32_t b1) {
    asm volatile(
        "mma.sync.aligned.m16n8k32.row.col.s32.s8.s8.s32 "
        "{%0,%1,%2,%3}, {%4,%5,%6,%7}, {%8,%9}, {%0,%1,%2,%3};"
        : "+r"(d[0]), "+r"(d[1]), "+r"(d[2]), "+r"(d[3])
        : "r"(a[0]), "r"(a[1]), "r"(a[2]), "r"(a[3]), "r"(b0), "r"(b1));
}
__device__ __forceinline__ void cpa16(uint32_t dst, const void* src, uint32_t ssz) {
    asm volatile("cp.async.cg.shared.global [%0], [%1], 16, %2;"
                 :: "r"(dst), "l"(src), "r"(ssz));
}

__global__ void zero_cnt_kernel() { if (threadIdx.x < 4) g_cnt[threadIdx.x] = 0; }

// ---------------- encoder (bit-exact) ----------------
__global__ void __launch_bounds__(256) enc_kernel(const float* __restrict__ f) {
    int idx = blockIdx.x * blockDim.x + threadIdx.x;
    if (idx >= BATCH * KP1) return;
    int b = idx / KP1, i = idx - b * KP1;
    unsigned m = 0;
    if (i < 784) {
        float x = f[b * 784 + i], v = 0.0f;
#pragma unroll
        for (int t = 0; t < TSTEPS; t++) {
            v += x;
            if (v >= 1.0f) { m |= (1u << t); v -= 1.0f; }
        }
    }
    g_M0[idx] = (uint16_t)m;
}

// ---------------- weight 2-limb s8 split, base 254 ----------------
__global__ void __launch_bounds__(32) wsplit(const float* __restrict__ W,
                                             int8_t* __restrict__ Q,
                                             float* __restrict__ S,
                                             int N, int K, int KP)
{
    int j = blockIdx.x, lane = threadIdx.x;
    const float* w = W + (size_t)j * K;
    float m = 0.0f;
    for (int k = lane; k < K; k += 32) m = fmaxf(m, fabsf(w[k]));
#pragma unroll
    for (int o = 16; o; o >>= 1) m = fmaxf(m, __shfl_xor_sync(~0u, m, o));
    float s0 = (m > 0.0f) ? m / 127.0f : 1.0f;
    if (lane == 0) S[j] = s0;
    double s0d = (double)s0;
    for (int k = lane; k < KP; k += 32) {
        double q0 = 0.0, q1 = 0.0;
        if (k < K) {
            double wd = (double)w[k];
            q0 = fmin(fmax(rint(wd / s0d), -127.0), 127.0);
            double r1 = wd - q0 * s0d;
            q1 = fmin(fmax(rint(r1 * 254.0 / s0d), -127.0), 127.0);
        }
        size_t base = (size_t)j * KP + k, lstr = (size_t)N * KP;
        Q[base]        = (int8_t)(int)q0;
        Q[base + lstr] = (int8_t)(int)q1;
    }
}

// ---------------- fused s8-GEMM + spiking scan + flagging ----------------
// grid: (BATCH/8, ceil(NOUT/64)); 256 threads. CTA M=128 (8b x 16t) x N=64.
template <int KP, int NOUT, bool IS_LAST, int LID>
__global__ void __launch_bounds__(256, 2) gemm_spike(
    const uint16_t* __restrict__ Min, const int8_t* __restrict__ Wq,
    const float* __restrict__ Sc, const float* __restrict__ bias,
    uint16_t* __restrict__ Mout, float* __restrict__ Out)
{
    extern __shared__ __align__(16) char sm[];
    constexpr int NPAN   = KP / 128;
    constexpr int MSK_B  = 8 * KP * 2;
    constexpr int OFF_A  = MSK_B;                 // 128 rows x pitch 144 s8
    constexpr int OFF_B  = OFF_A + 128 * 144;     // 2 bufs x 2 limbs x 64 x 144
    constexpr int OFF_SC = OFF_B + 2 * 2 * 64 * 144;
    constexpr int OFF_C  = OFF_A;                 // scan buf reuses A+B region
    constexpr int BBUF   = 2 * 64 * 144;          // 18432

    const uint32_t sbase = smem_u32(sm);
    const int tid  = threadIdx.x;
    const int lane = tid & 31, wm = tid >> 5;
    const int g = lane >> 2, tg = lane & 3;
    const int b0 = blockIdx.x * 8;
    const int n0 = blockIdx.y * 64;

    {
        const uint4* msrc = (const uint4*)(Min + (size_t)b0 * KP);
        uint4* mdst = (uint4*)sm;
        for (int u = tid; u < MSK_B / 16; u += 256) mdst[u] = msrc[u];
    }
    if (tid < 64) {
        int j = n0 + tid;
        float s = (j < NOUT) ? Sc[j] : 0.0f;
        ((float*)(sm + OFF_SC))[tid]       = s;
        ((float*)(sm + OFF_SC))[64 + tid]  = s * (1.0f / 254.0f);
        ((float*)(sm + OFF_SC))[128 + tid] = (j < NOUT) ? bias[j] : 0.0f;
    }
    auto loadB = [&](int p, int buf) {
        const int bk = p * 128;
        for (int v = tid; v < 1024; v += 256) {
            int l = v >> 9, rem = v & 511, r = rem >> 3, cs = rem & 7;
            int row = n0 + r;
            uint32_t ssz = (row < NOUT) ? 16u : 0u;
            int rc = row < NOUT ? row : 0;
            const int8_t* src = Wq + ((size_t)l * NOUT + rc) * KP + bk + cs * 16;
            cpa16(sbase + OFF_B + buf * BBUF + l * 9216 + r * 144 + cs * 16, src, ssz);
        }
        asm volatile("cp.async.commit_group;");
    };
    loadB(0, 0);
    __syncthreads();

    int D0[8][4], D1[8][4];
#pragma unroll
    for (int ni = 0; ni < 8; ni++)
#pragma unroll
        for (int r = 0; r < 4; r++) { D0[ni][r] = 0; D1[ni][r] = 0; }

#pragma unroll 1
    for (int p = 0; p < NPAN; p++) {
        const int buf = p & 1;
        // expand A panel: bitmask bit t -> s8 rows
        {
            const uint64_t* m64 = (const uint64_t*)sm;
            int bl = tid >> 5, kq = tid & 31;
            uint64_t mv = m64[bl * (KP / 4) + p * 32 + kq];
            uint32_t lo = (uint32_t)mv, hi = (uint32_t)(mv >> 32);
            char* arow = sm + OFF_A + (bl * 16) * 144 + kq * 4;
#pragma unroll
            for (int t = 0; t < 16; t++) {
                uint32_t xl = (lo >> t) & 0x00010001u; xl |= xl >> 15;
                uint32_t xh = (hi >> t) & 0x00010001u; xh |= xh >> 15;
                uint32_t nib = (xl & 3u) | ((xh & 3u) << 2);
                *(uint32_t*)(arow + t * 144) = (nib * 0x00204081u) & 0x01010101u;
            }
        }
        if (p + 1 < NPAN) {
            loadB(p + 1, buf ^ 1);
            asm volatile("cp.async.wait_group 1;");
        } else {
            asm volatile("cp.async.wait_group 0;");
        }
        __syncthreads();

#pragma unroll
        for (int ch = 0; ch < 4; ch++) {
            uint32_t afr[4];
            const char* ab = sm + OFF_A + (wm * 16) * 144 + ch * 32;
            afr[0] = *(const uint32_t*)(ab + g * 144 + tg * 4);
            afr[1] = *(const uint32_t*)(ab + (g + 8) * 144 + tg * 4);
            afr[2] = *(const uint32_t*)(ab + g * 144 + 16 + tg * 4);
            afr[3] = *(const uint32_t*)(ab + (g + 8) * 144 + 16 + tg * 4);
#pragma unroll
            for (int ni = 0; ni < 8; ni++) {
                const char* bb = sm + OFF_B + buf * BBUF + (ni * 8 + g) * 144 + ch * 32;
                uint32_t b00 = *(const uint32_t*)(bb + tg * 4);
                uint32_t b01 = *(const uint32_t*)(bb + 16 + tg * 4);
                uint32_t b10 = *(const uint32_t*)(bb + 9216 + tg * 4);
                uint32_t b11 = *(const uint32_t*)(bb + 9216 + 16 + tg * 4);
                mma8(D0[ni], afr, b00, b01);
                mma8(D1[ni], afr, b10, b11);
            }
        }
        __syncthreads();
    }

    // combine limbs and store to scan buffer
    float* cs = (float*)(sm + OFF_C);
    const float* s0a = (const float*)(sm + OFF_SC);
    const float* s1a = (const float*)(sm + OFF_SC) + 64;
#pragma unroll
    for (int ni = 0; ni < 8; ni++)
#pragma unroll
        for (int r = 0; r < 4; r++) {
            int row = wm * 16 + g + (r >> 1) * 8;
            int col = ni * 8 + tg * 2 + (r & 1);
            cs[row * 64 + col] = s0a[col] * (float)D0[ni][r] + s1a[col] * (float)D1[ni][r];
        }
    __syncthreads();

    // sequential t-scan + near-threshold flagging
    const float* ba = (const float*)(sm + OFF_SC) + 128;
#pragma unroll
    for (int u = 0; u < 2; u++) {
        int pr = tid + 256 * u;
        int j = pr & 63, bl = pr >> 6;
        float bj = ba[j];
        const float* colp = cs + bl * 16 * 64 + j;
        float v = 0.0f;
        uint32_t msk = 0;
        bool flag = false;
#pragma unroll
        for (int t = 0; t < 16; t++) {
            v = (v + colp[t * 64]) + bj;
            flag |= (fabsf(v - 1.0f) < EPS);
            if (v >= 1.0f) { msk |= (1u << t); v -= 1.0f; }
        }
        int jj = n0 + j;
        if (jj < NOUT) {
            int b = b0 + bl;
            if (IS_LAST)
                Out[(size_t)b * NOUT + jj] = (float)__popc(msk) * 0.0625f;
            else
                Mout[(size_t)b * NOUT + jj] = (uint16_t)msk;
            if (flag) {
                int s = atomicAdd(&g_cnt[LID], 1);
                if (s < FCAP) g_flag[LID][s] = ((uint32_t)b << 10) | (uint32_t)jj;
            }
        }
    }
}

// ---------------- repair: recompute flagged chains with reference bits -----
template <int KP, int K, int NOUT, bool IS_LAST, int LID>
__global__ void __launch_bounds__(256) repair_kernel(
    const uint16_t* __restrict__ Min, const float* __restrict__ W,
    const float* __restrict__ bias, uint16_t* __restrict__ Mout,
    float* __restrict__ Out)
{
    int n = g_cnt[LID];
    if (n > FCAP) n = FCAP;
    for (int s = blockIdx.x * blockDim.x + threadIdx.x; s < n;
         s += gridDim.x * blockDim.x) {
        uint32_t pk = g_flag[LID][s];
        int b = (int)(pk >> 10), j = (int)(pk & 1023u);
        const uint16_t* mrow = Min + (size_t)b * KP;
        const float* wr = W + (size_t)j * K;
        float acc[TSTEPS];
#pragma unroll
        for (int t = 0; t < TSTEPS; t++) acc[t] = 0.0f;
        for (int i = 0; i < K; i++) {
            unsigned m = mrow[i];
            if (!m) continue;          // adding 0.0f*w terms is a bit-exact no-op
            float w = wr[i];
#pragma unroll
            for (int t = 0; t < TSTEPS; t++)
                if (m & (1u << t)) acc[t] += w;
        }
        float bj = bias[j], v = 0.0f;
        uint32_t msk = 0;
#pragma unroll
        for (int t = 0; t < TSTEPS; t++) {
            v = (v + acc[t]) + bj;
            if (v >= 1.0f) { msk |= (1u << t); v -= 1.0f; }
        }
        if (IS_LAST)
            Out[(size_t)b * NOUT + j] = (float)__popc(msk) * 0.0625f;
        else
            Mout[(size_t)b * NOUT + j] = (uint16_t)msk;
    }
}

// ---------------------------------------------------------------------------
extern "C" void kernel_launch(void* const* d_in, const int* in_sizes, int n_in,
                              void* d_out, int out_size)
{
    const float* features = (const float*)d_in[0];
    const float* W1 = (const float*)d_in[1];
    const float* b1 = (const float*)d_in[2];
    const float* W2 = (const float*)d_in[3];
    const float* b2 = (const float*)d_in[4];
    const float* W3 = (const float*)d_in[5];
    const float* b3 = (const float*)d_in[6];
    const float* W4 = (const float*)d_in[7];
    const float* b4 = (const float*)d_in[8];
    float* out = (float*)d_out;

    uint16_t *m0, *m1, *m2, *m3;
    int8_t *q1, *q2, *q3, *q4;
    float *s1, *s2, *s3, *s4;
    cudaGetSymbolAddress((void**)&m0, g_M0);
    cudaGetSymbolAddress((void**)&m1, g_M1);
    cudaGetSymbolAddress((void**)&m2, g_M2);
    cudaGetSymbolAddress((void**)&m3, g_M3);
    cudaGetSymbolAddress((void**)&q1, g_Q1);
    cudaGetSymbolAddress((void**)&q2, g_Q2);
    cudaGetSymbolAddress((void**)&q3, g_Q3);
    cudaGetSymbolAddress((void**)&q4, g_Q4);
    cudaGetSymbolAddress((void**)&s1, g_S1);
    cudaGetSymbolAddress((void**)&s2, g_S2);
    cudaGetSymbolAddress((void**)&s3, g_S3);
    cudaGetSymbolAddress((void**)&s4, g_S4);

    zero_cnt_kernel<<<1, 32>>>();
    enc_kernel<<<(BATCH * KP1 + 255) / 256, 256>>>(features);
    wsplit<<<128, 32>>>(W1, q1, s1, 128, 784, KP1);
    wsplit<<<128, 32>>>(W2, q2, s2, 128, 128, 128);
    wsplit<<<128, 32>>>(W3, q3, s3, 128, 128, 128);
    wsplit<<<784, 32>>>(W4, q4, s4, 784, 128, 128);

    constexpr int SM_L1 = 8 * KP1 * 2 + 128 * 144 + 2 * 2 * 64 * 144 + 768;
    constexpr int SM_H  = 8 * 128 * 2 + 128 * 144 + 2 * 2 * 64 * 144 + 768;

    cudaFuncSetAttribute(gemm_spike<KP1, 128, false, 0>,
                         cudaFuncAttributeMaxDynamicSharedMemorySize, SM_L1);
    cudaFuncSetAttribute(gemm_spike<128, 128, false, 1>,
                         cudaFuncAttributeMaxDynamicSharedMemorySize, SM_H);
    cudaFuncSetAttribute(gemm_spike<128, 128, false, 2>,
                         cudaFuncAttributeMaxDynamicSharedMemorySize, SM_H);
    cudaFuncSetAttribute(gemm_spike<128, 784, true, 3>,
                         cudaFuncAttributeMaxDynamicSharedMemorySize, SM_H);

    gemm_spike<KP1, 128, false, 0>
        <<<dim3(BATCH / 8, 2), 256, SM_L1>>>(m0, q1, s1, b1, m1, nullptr);
    repair_kernel<KP1, 784, 128, false, 0><<<256, 256>>>(m0, W1, b1, m1, nullptr);

    gemm_spike<128, 128, false, 1>
        <<<dim3(BATCH / 8, 2), 256, SM_H>>>(m1, q2, s2, b2, m2, nullptr);
    repair_kernel<128, 128, 128, false, 1><<<256, 256>>>(m1, W2, b2, m2, nullptr);

    gemm_spike<128, 128, false, 2>
        <<<dim3(BATCH / 8, 2), 256, SM_H>>>(m2, q3, s3, b3, m3, nullptr);
    repair_kernel<128, 128, 128, false, 2><<<256, 256>>>(m2, W3, b3, m3, nullptr);

    gemm_spike<128, 784, true, 3>
        <<<dim3(BATCH / 8, 13), 256, SM_H>>>(m3, q4, s4, b4, nullptr, out);
    repair_kernel<128, 128, 784, true, 3><<<256, 256>>>(m3, W4, b4, nullptr, out);
}

// round 8
// speedup vs baseline: 1.2152x; 1.0904x over previous
#include <cuda_runtime.h>
#include <stdint.h>

// AE_spikes via mma.sync s8 tensor cores. Layers = GEMM over rows (t,b).
// Weights: 2 s8 limbs base 254; per-limb exact int32 accumulators; combined
// once. Fire-and-reset scan fused in epilogue; membranes within EPS of
// threshold repaired with bit-exact reference fp32 semantics.
// R7: warp-tile 32x32 (B-fragment loads amortized over 2 A-frags) and
// t-parallel warp repair (16 lanes = 16 timesteps, broadcast mask reads).

#define BATCH  16384
#define TSTEPS 16
#define KP1    896        // 784 padded to 7*128
#define EPS    1e-3f
#define FCAP   1048576

// ---------------- scratch ----------------
__device__ uint16_t g_M0[BATCH * KP1];
__device__ uint16_t g_M1[BATCH * 128];
__device__ uint16_t g_M2[BATCH * 128];
__device__ uint16_t g_M3[BATCH * 128];
__device__ int8_t   g_Q1[2 * 128 * KP1];
__device__ int8_t   g_Q2[2 * 128 * 128];
__device__ int8_t   g_Q3[2 * 128 * 128];
__device__ int8_t   g_Q4[2 * 784 * 128];
__device__ float    g_S1[128], g_S2[128], g_S3[128], g_S4[784];
__device__ int      g_cnt[4];
__device__ uint32_t g_flag[4][FCAP];

// ---------------- helpers ----------------
__device__ __forceinline__ uint32_t smem_u32(const void* p) {
    uint32_t a;
    asm("{ .reg .u64 t; cvta.to.shared.u64 t, %1; cvt.u32.u64 %0, t; }"
        : "=r"(a) : "l"(p));
    return a;
}
__device__ __forceinline__ void mma8(int* d, const uint32_t* a, uint32_t b0, uint32_t b1) {
    asm volatile(
        "mma.sync.aligned.m16n8k32.row.col.s32.s8.s8.s32 "
        "{%0,%1,%2,%3}, {%4,%5,%6,%7}, {%8,%9}, {%0,%1,%2,%3};"
        : "+r"(d[0]), "+r"(d[1]), "+r"(d[2]), "+r"(d[3])
        : "r"(a[0]), "r"(a[1]), "r"(a[2]), "r"(a[3]), "r"(b0), "r"(b1));
}
__device__ __forceinline__ void cpa16(uint32_t dst, const void* src, uint32_t ssz) {
    asm volatile("cp.async.cg.shared.global [%0], [%1], 16, %2;"
                 :: "r"(dst), "l"(src), "r"(ssz));
}

__global__ void zero_cnt_kernel() { if (threadIdx.x < 4) g_cnt[threadIdx.x] = 0; }

// ---------------- encoder (bit-exact) ----------------
__global__ void __launch_bounds__(256) enc_kernel(const float* __restrict__ f) {
    int idx = blockIdx.x * blockDim.x + threadIdx.x;
    if (idx >= BATCH * KP1) return;
    int b = idx / KP1, i = idx - b * KP1;
    unsigned m = 0;
    if (i < 784) {
        float x = f[b * 784 + i], v = 0.0f;
#pragma unroll
        for (int t = 0; t < TSTEPS; t++) {
            v += x;
            if (v >= 1.0f) { m |= (1u << t); v -= 1.0f; }
        }
    }
    g_M0[idx] = (uint16_t)m;
}

// ---------------- weight 2-limb s8 split, base 254 ----------------
__global__ void __launch_bounds__(32) wsplit(const float* __restrict__ W,
                                             int8_t* __restrict__ Q,
                                             float* __restrict__ S,
                                             int N, int K, int KP)
{
    int j = blockIdx.x, lane = threadIdx.x;
    const float* w = W + (size_t)j * K;
    float m = 0.0f;
    for (int k = lane; k < K; k += 32) m = fmaxf(m, fabsf(w[k]));
#pragma unroll
    for (int o = 16; o; o >>= 1) m = fmaxf(m, __shfl_xor_sync(~0u, m, o));
    float s0 = (m > 0.0f) ? m / 127.0f : 1.0f;
    if (lane == 0) S[j] = s0;
    double s0d = (double)s0;
    for (int k = lane; k < KP; k += 32) {
        double q0 = 0.0, q1 = 0.0;
        if (k < K) {
            double wd = (double)w[k];
            q0 = fmin(fmax(rint(wd / s0d), -127.0), 127.0);
            double r1 = wd - q0 * s0d;
            q1 = fmin(fmax(rint(r1 * 254.0 / s0d), -127.0), 127.0);
        }
        size_t base = (size_t)j * KP + k, lstr = (size_t)N * KP;
        Q[base]        = (int8_t)(int)q0;
        Q[base + lstr] = (int8_t)(int)q1;
    }
}

// ---------------- fused s8-GEMM + spiking scan + flagging ----------------
// grid: (BATCH/8, ceil(NOUT/64)); 256 threads. CTA M=128 (8b x 16t) x N=64.
// Warp grid 4(M) x 2(N): warp tile 32x32, 2 A-frags amortize B-frag loads.
template <int KP, int NOUT, bool IS_LAST, int LID>
__global__ void __launch_bounds__(256, 2) gemm_spike(
    const uint16_t* __restrict__ Min, const int8_t* __restrict__ Wq,
    const float* __restrict__ Sc, const float* __restrict__ bias,
    uint16_t* __restrict__ Mout, float* __restrict__ Out)
{
    extern __shared__ __align__(16) char sm[];
    constexpr int NPAN   = KP / 128;
    constexpr int MSK_B  = 8 * KP * 2;
    constexpr int OFF_A  = MSK_B;                 // 128 rows x pitch 144 s8
    constexpr int OFF_B  = OFF_A + 128 * 144;     // 2 bufs x 2 limbs x 64 x 144
    constexpr int OFF_SC = OFF_B + 2 * 2 * 64 * 144;
    constexpr int OFF_C  = OFF_A;                 // scan buf reuses A+B region
    constexpr int BBUF   = 2 * 64 * 144;          // 18432

    const uint32_t sbase = smem_u32(sm);
    const int tid  = threadIdx.x;
    const int lane = tid & 31, wid = tid >> 5;
    const int wm2 = wid >> 1, wn = wid & 1;       // 4 x 2 warp grid
    const int g = lane >> 2, tg = lane & 3;
    const int b0 = blockIdx.x * 8;
    const int n0 = blockIdx.y * 64;

    {
        const uint4* msrc = (const uint4*)(Min + (size_t)b0 * KP);
        uint4* mdst = (uint4*)sm;
        for (int u = tid; u < MSK_B / 16; u += 256) mdst[u] = msrc[u];
    }
    if (tid < 64) {
        int j = n0 + tid;
        float s = (j < NOUT) ? Sc[j] : 0.0f;
        ((float*)(sm + OFF_SC))[tid]       = s;
        ((float*)(sm + OFF_SC))[64 + tid]  = s * (1.0f / 254.0f);
        ((float*)(sm + OFF_SC))[128 + tid] = (j < NOUT) ? bias[j] : 0.0f;
    }
    auto loadB = [&](int p, int buf) {
        const int bk = p * 128;
        for (int v = tid; v < 1024; v += 256) {
            int l = v >> 9, rem = v & 511, r = rem >> 3, cs = rem & 7;
            int row = n0 + r;
            uint32_t ssz = (row < NOUT) ? 16u : 0u;
            int rc = row < NOUT ? row : 0;
            const int8_t* src = Wq + ((size_t)l * NOUT + rc) * KP + bk + cs * 16;
            cpa16(sbase + OFF_B + buf * BBUF + l * 9216 + r * 144 + cs * 16, src, ssz);
        }
        asm volatile("cp.async.commit_group;");
    };
    loadB(0, 0);
    __syncthreads();

    int D0[2][4][4], D1[2][4][4];
#pragma unroll
    for (int mi = 0; mi < 2; mi++)
#pragma unroll
        for (int ni = 0; ni < 4; ni++)
#pragma unroll
            for (int r = 0; r < 4; r++) { D0[mi][ni][r] = 0; D1[mi][ni][r] = 0; }

#pragma unroll 1
    for (int p = 0; p < NPAN; p++) {
        const int buf = p & 1;
        // expand A panel: bitmask bit t -> s8 rows
        {
            const uint64_t* m64 = (const uint64_t*)sm;
            int bl = tid >> 5, kq = tid & 31;
            uint64_t mv = m64[bl * (KP / 4) + p * 32 + kq];
            uint32_t lo = (uint32_t)mv, hi = (uint32_t)(mv >> 32);
            char* arow = sm + OFF_A + (bl * 16) * 144 + kq * 4;
#pragma unroll
            for (int t = 0; t < 16; t++) {
                uint32_t xl = (lo >> t) & 0x00010001u; xl |= xl >> 15;
                uint32_t xh = (hi >> t) & 0x00010001u; xh |= xh >> 15;
                uint32_t nib = (xl & 3u) | ((xh & 3u) << 2);
                *(uint32_t*)(arow + t * 144) = (nib * 0x00204081u) & 0x01010101u;
            }
        }
        if (p + 1 < NPAN) {
            loadB(p + 1, buf ^ 1);
            asm volatile("cp.async.wait_group 1;");
        } else {
            asm volatile("cp.async.wait_group 0;");
        }
        __syncthreads();

#pragma unroll
        for (int ch = 0; ch < 4; ch++) {
            uint32_t afr[2][4];
#pragma unroll
            for (int mi = 0; mi < 2; mi++) {
                const char* ab = sm + OFF_A + (wm2 * 32 + mi * 16) * 144 + ch * 32;
                afr[mi][0] = *(const uint32_t*)(ab + g * 144 + tg * 4);
                afr[mi][1] = *(const uint32_t*)(ab + (g + 8) * 144 + tg * 4);
                afr[mi][2] = *(const uint32_t*)(ab + g * 144 + 16 + tg * 4);
                afr[mi][3] = *(const uint32_t*)(ab + (g + 8) * 144 + 16 + tg * 4);
            }
#pragma unroll
            for (int ni = 0; ni < 4; ni++) {
                const char* bb = sm + OFF_B + buf * BBUF +
                                 (wn * 32 + ni * 8 + g) * 144 + ch * 32;
                uint32_t b00 = *(const uint32_t*)(bb + tg * 4);
                uint32_t b01 = *(const uint32_t*)(bb + 16 + tg * 4);
                uint32_t b10 = *(const uint32_t*)(bb + 9216 + tg * 4);
                uint32_t b11 = *(const uint32_t*)(bb + 9216 + 16 + tg * 4);
                mma8(D0[0][ni], afr[0], b00, b01);
                mma8(D0[1][ni], afr[1], b00, b01);
                mma8(D1[0][ni], afr[0], b10, b11);
                mma8(D1[1][ni], afr[1], b10, b11);
            }
        }
        __syncthreads();
    }

    // combine limbs and store to scan buffer
    float* cs = (float*)(sm + OFF_C);
    const float* s0a = (const float*)(sm + OFF_SC);
    const float* s1a = (const float*)(sm + OFF_SC) + 64;
#pragma unroll
    for (int mi = 0; mi < 2; mi++)
#pragma unroll
        for (int ni = 0; ni < 4; ni++)
#pragma unroll
            for (int r = 0; r < 4; r++) {
                int row = wm2 * 32 + mi * 16 + g + (r >> 1) * 8;
                int col = wn * 32 + ni * 8 + tg * 2 + (r & 1);
                cs[row * 64 + col] = s0a[col] * (float)D0[mi][ni][r] +
                                     s1a[col] * (float)D1[mi][ni][r];
            }
    __syncthreads();

    // sequential t-scan + near-threshold flagging
    const float* ba = (const float*)(sm + OFF_SC) + 128;
#pragma unroll
    for (int u = 0; u < 2; u++) {
        int pr = tid + 256 * u;
        int j = pr & 63, bl = pr >> 6;
        float bj = ba[j];
        const float* colp = cs + bl * 16 * 64 + j;
        float v = 0.0f;
        uint32_t msk = 0;
        bool flag = false;
#pragma unroll
        for (int t = 0; t < 16; t++) {
            v = (v + colp[t * 64]) + bj;
            flag |= (fabsf(v - 1.0f) < EPS);
            if (v >= 1.0f) { msk |= (1u << t); v -= 1.0f; }
        }
        int jj = n0 + j;
        if (jj < NOUT) {
            int b = b0 + bl;
            if (IS_LAST)
                Out[(size_t)b * NOUT + jj] = (float)__popc(msk) * 0.0625f;
            else
                Mout[(size_t)b * NOUT + jj] = (uint16_t)msk;
            if (flag) {
                int s = atomicAdd(&g_cnt[LID], 1);
                if (s < FCAP) g_flag[LID][s] = ((uint32_t)b << 10) | (uint32_t)jj;
            }
        }
    }
}

// ---------------- repair: t-parallel, warp = 2 flagged pairs ---------------
// Lanes 0-15 handle pair A (lane = timestep), lanes 16-31 pair B. Each lane
// accumulates its timestep's terms in ascending-i order (bit-exact reference
// semantics); mask/weight reads are 16-lane broadcasts. Lane 0 of each group
// gathers acc[t] via shfl and runs the fire-and-reset scan.
template <int KP, int K, int NOUT, bool IS_LAST, int LID>
__global__ void __launch_bounds__(256) repair_kernel(
    const uint16_t* __restrict__ Min, const float* __restrict__ W,
    const float* __restrict__ bias, uint16_t* __restrict__ Mout,
    float* __restrict__ Out)
{
    int n = g_cnt[LID];
    if (n > FCAP) n = FCAP;
    const int lane = threadIdx.x & 31;
    const int grp = lane >> 4, tl = lane & 15;
    const int wglob = (blockIdx.x * blockDim.x + threadIdx.x) >> 5;
    const int nwarps = (gridDim.x * blockDim.x) >> 5;

    for (int s0 = wglob * 2; s0 < n; s0 += nwarps * 2) {
        int s = s0 + grp;
        float acc = 0.0f;
        int b = 0, j = 0;
        bool active = (s < n);
        if (active) {
            uint32_t pk = g_flag[LID][s];
            b = (int)(pk >> 10); j = (int)(pk & 1023u);
            const uint16_t* mrow = Min + (size_t)b * KP;
            const float* wr = W + (size_t)j * K;
            const uint32_t bit = 1u << tl;
            for (int i = 0; i < K; i++) {
                unsigned m = mrow[i];                 // 16-lane broadcast
                if (m & bit) acc += wr[i];            // ascending-i, bit-exact
            }
        }
        // lane 0 of each 16-lane group runs the scan
        float bj = active ? bias[j] : 0.0f;
        float v = 0.0f;
        uint32_t msk = 0;
#pragma unroll
        for (int t = 0; t < TSTEPS; t++) {
            float a = __shfl_sync(0xFFFFFFFFu, acc, (lane & 16) + t);
            v = (v + a) + bj;
            if (v >= 1.0f) { msk |= (1u << t); v -= 1.0f; }
        }
        if (active && tl == 0) {
            if (IS_LAST)
                Out[(size_t)b * NOUT + j] = (float)__popc(msk) * 0.0625f;
            else
                Mout[(size_t)b * NOUT + j] = (uint16_t)msk;
        }
    }
}

// ---------------------------------------------------------------------------
extern "C" void kernel_launch(void* const* d_in, const int* in_sizes, int n_in,
                              void* d_out, int out_size)
{
    const float* features = (const float*)d_in[0];
    const float* W1 = (const float*)d_in[1];
    const float* b1 = (const float*)d_in[2];
    const float* W2 = (const float*)d_in[3];
    const float* b2 = (const float*)d_in[4];
    const float* W3 = (const float*)d_in[5];
    const float* b3 = (const float*)d_in[6];
    const float* W4 = (const float*)d_in[7];
    const float* b4 = (const float*)d_in[8];
    float* out = (float*)d_out;

    uint16_t *m0, *m1, *m2, *m3;
    int8_t *q1, *q2, *q3, *q4;
    float *s1, *s2, *s3, *s4;
    cudaGetSymbolAddress((void**)&m0, g_M0);
    cudaGetSymbolAddress((void**)&m1, g_M1);
    cudaGetSymbolAddress((void**)&m2, g_M2);
    cudaGetSymbolAddress((void**)&m3, g_M3);
    cudaGetSymbolAddress((void**)&q1, g_Q1);
    cudaGetSymbolAddress((void**)&q2, g_Q2);
    cudaGetSymbolAddress((void**)&q3, g_Q3);
    cudaGetSymbolAddress((void**)&q4, g_Q4);
    cudaGetSymbolAddress((void**)&s1, g_S1);
    cudaGetSymbolAddress((void**)&s2, g_S2);
    cudaGetSymbolAddress((void**)&s3, g_S3);
    cudaGetSymbolAddress((void**)&s4, g_S4);

    zero_cnt_kernel<<<1, 32>>>();
    enc_kernel<<<(BATCH * KP1 + 255) / 256, 256>>>(features);
    wsplit<<<128, 32>>>(W1, q1, s1, 128, 784, KP1);
    wsplit<<<128, 32>>>(W2, q2, s2, 128, 128, 128);
    wsplit<<<128, 32>>>(W3, q3, s3, 128, 128, 128);
    wsplit<<<784, 32>>>(W4, q4, s4, 784, 128, 128);

    constexpr int SM_L1 = 8 * KP1 * 2 + 128 * 144 + 2 * 2 * 64 * 144 + 768;
    constexpr int SM_H  = 8 * 128 * 2 + 128 * 144 + 2 * 2 * 64 * 144 + 768;

    cudaFuncSetAttribute(gemm_spike<KP1, 128, false, 0>,
                         cudaFuncAttributeMaxDynamicSharedMemorySize, SM_L1);
    cudaFuncSetAttribute(gemm_spike<128, 128, false, 1>,
                         cudaFuncAttributeMaxDynamicSharedMemorySize, SM_H);
    cudaFuncSetAttribute(gemm_spike<128, 128, false, 2>,
                         cudaFuncAttributeMaxDynamicSharedMemorySize, SM_H);
    cudaFuncSetAttribute(gemm_spike<128, 784, true, 3>,
                         cudaFuncAttributeMaxDynamicSharedMemorySize, SM_H);

    gemm_spike<KP1, 128, false, 0>
        <<<dim3(BATCH / 8, 2), 256, SM_L1>>>(m0, q1, s1, b1, m1, nullptr);
    repair_kernel<KP1, 784, 128, false, 0><<<296, 256>>>(m0, W1, b1, m1, nullptr);

    gemm_spike<128, 128, false, 1>
        <<<dim3(BATCH / 8, 2), 256, SM_H>>>(m1, q2, s2, b2, m2, nullptr);
    repair_kernel<128, 128, 128, false, 1><<<296, 256>>>(m1, W2, b2, m2, nullptr);

    gemm_spike<128, 128, false, 2>
        <<<dim3(BATCH / 8, 2), 256, SM_H>>>(m2, q3, s3, b3, m3, nullptr);
    repair_kernel<128, 128, 128, false, 2><<<296, 256>>>(m2, W3, b3, m3, nullptr);

    gemm_spike<128, 784, true, 3>
        <<<dim3(BATCH / 8, 13), 256, SM_H>>>(m3, q4, s4, b4, nullptr, out);
    repair_kernel<128, 128, 784, true, 3><<<296, 256>>>(m3, W4, b4, nullptr, out);
}

// round 10
// speedup vs baseline: 1.3831x; 1.1381x over previous
#include <cuda_runtime.h>
#include <stdint.h>

// AE_spikes via mma.sync s8 tensor cores. Layers = GEMM over rows (t,b).
// 2 s8 weight limbs base 254; exact per-limb int32 accumulation; fused
// fire-and-reset scan; near-threshold flag + bit-exact repair => rel_err 0.
// R9 = R8 with the expansion overflow fixed: per-t select shifts BEFORE
// widening (the hi<<8 pre-shift lost m3's bits for t>=8).

#define BATCH  16384
#define TSTEPS 16
#define KP1    896
#define EPS    1e-3f
#define FCAP   1048576

// ---------------- scratch ----------------
__device__ uint16_t g_M0[BATCH * KP1];
__device__ uint16_t g_M1[BATCH * 128];
__device__ uint16_t g_M2[BATCH * 128];
__device__ uint16_t g_M3[BATCH * 128];
__device__ int8_t   g_Q1[2 * 128 * KP1];
__device__ int8_t   g_Q2[2 * 128 * 128];
__device__ int8_t   g_Q3[2 * 128 * 128];
__device__ int8_t   g_Q4[2 * 784 * 128];
__device__ float    g_S1[128], g_S2[128], g_S3[128], g_S4[784];
__device__ int      g_cnt[4];
__device__ uint32_t g_flag[4][FCAP];

// ---------------- helpers ----------------
__device__ __forceinline__ uint32_t smem_u32(const void* p) {
    uint32_t a;
    asm("{ .reg .u64 t; cvta.to.shared.u64 t, %1; cvt.u32.u64 %0, t; }"
        : "=r"(a) : "l"(p));
    return a;
}
__device__ __forceinline__ void mma8(int* d, const uint32_t* a, uint32_t b0, uint32_t b1) {
    asm volatile(
        "mma.sync.aligned.m16n8k32.row.col.s32.s8.s8.s32 "
        "{%0,%1,%2,%3}, {%4,%5,%6,%7}, {%8,%9}, {%0,%1,%2,%3};"
        : "+r"(d[0]), "+r"(d[1]), "+r"(d[2]), "+r"(d[3])
        : "r"(a[0]), "r"(a[1]), "r"(a[2]), "r"(a[3]), "r"(b0), "r"(b1));
}
__device__ __forceinline__ void cpa16(uint32_t dst, const void* src, uint32_t ssz) {
    asm volatile("cp.async.cg.shared.global [%0], [%1], 16, %2;"
                 :: "r"(dst), "l"(src), "r"(ssz));
}

__global__ void zero_cnt_kernel() { if (threadIdx.x < 4) g_cnt[threadIdx.x] = 0; }

// ---------------- encoder (bit-exact) ----------------
__global__ void __launch_bounds__(256) enc_kernel(const float* __restrict__ f) {
    int idx = blockIdx.x * blockDim.x + threadIdx.x;
    if (idx >= BATCH * KP1) return;
    int b = idx / KP1, i = idx - b * KP1;
    unsigned m = 0;
    if (i < 784) {
        float x = f[b * 784 + i], v = 0.0f;
#pragma unroll
        for (int t = 0; t < TSTEPS; t++) {
            v += x;
            if (v >= 1.0f) { m |= (1u << t); v -= 1.0f; }
        }
    }
    g_M0[idx] = (uint16_t)m;
}

// ---------------- weight 2-limb s8 split, base 254 ----------------
__global__ void __launch_bounds__(32) wsplit(const float* __restrict__ W,
                                             int8_t* __restrict__ Q,
                                             float* __restrict__ S,
                                             int N, int K, int KP)
{
    int j = blockIdx.x, lane = threadIdx.x;
    const float* w = W + (size_t)j * K;
    float m = 0.0f;
    for (int k = lane; k < K; k += 32) m = fmaxf(m, fabsf(w[k]));
#pragma unroll
    for (int o = 16; o; o >>= 1) m = fmaxf(m, __shfl_xor_sync(~0u, m, o));
    float s0 = (m > 0.0f) ? m / 127.0f : 1.0f;
    if (lane == 0) S[j] = s0;
    double s0d = (double)s0;
    for (int k = lane; k < KP; k += 32) {
        double q0 = 0.0, q1 = 0.0;
        if (k < K) {
            double wd = (double)w[k];
            q0 = fmin(fmax(rint(wd / s0d), -127.0), 127.0);
            double r1 = wd - q0 * s0d;
            q1 = fmin(fmax(rint(r1 * 254.0 / s0d), -127.0), 127.0);
        }
        size_t base = (size_t)j * KP + k, lstr = (size_t)N * KP;
        Q[base]        = (int8_t)(int)q0;
        Q[base + lstr] = (int8_t)(int)q1;
    }
}

// ---------------- shared device pieces ----------------
// Masks stored PERMUTED per u64: lo=(m0,m2), hi=(m1,m3). Per t the output
// word bytes must be (m0_t, m1_t, m2_t, m3_t):
//   a = (lo>>t)&0x00010001  -> bytes 0,2 = m0_t, m2_t
//   b = (hi>>t)&0x00010001  -> m1_t, m3_t (still in bytes 0,2)
//   w = a | (b<<8)          -> b moves to bytes 1,3. No overflow for any t.
__device__ __forceinline__ void expand_panel(const char* mskbase, char* abase,
                                             int kpu64, int p, int tid) {
    const uint64_t* m64 = (const uint64_t*)mskbase;
    int bl = tid >> 5, kq = tid & 31;
    uint64_t mv = m64[bl * kpu64 + p * 32 + kq];
    uint32_t lo = (uint32_t)mv;
    uint32_t hi = (uint32_t)(mv >> 32);
    char* arow = abase + (bl * 16) * 144 + kq * 4;
#pragma unroll
    for (int t = 0; t < 16; t++) {
        uint32_t a = (lo >> t) & 0x00010001u;
        uint32_t b = (hi >> t) & 0x00010001u;
        *(uint32_t*)(arow + t * 144) = a | (b << 8);
    }
}

// warp mma over one K=128 panel: A at abase, B limbs at bbase/bbase+9216.
template <typename T>
__device__ __forceinline__ void mma_panel(const char* abase, const char* bbase,
                                          int wm2, int wn, int g, int tg,
                                          int (&D0)[2][4][4], int (&D1)[2][4][4]) {
#pragma unroll
    for (int ch = 0; ch < 4; ch++) {
        uint32_t afr[2][4];
#pragma unroll
        for (int mi = 0; mi < 2; mi++) {
            const char* ab = abase + (wm2 * 32 + mi * 16) * 144 + ch * 32;
            afr[mi][0] = *(const uint32_t*)(ab + g * 144 + tg * 4);
            afr[mi][1] = *(const uint32_t*)(ab + (g + 8) * 144 + tg * 4);
            afr[mi][2] = *(const uint32_t*)(ab + g * 144 + 16 + tg * 4);
            afr[mi][3] = *(const uint32_t*)(ab + (g + 8) * 144 + 16 + tg * 4);
        }
#pragma unroll
        for (int ni = 0; ni < 4; ni++) {
            const char* bb = bbase + (wn * 32 + ni * 8 + g) * 144 + ch * 32;
            uint32_t b00 = *(const uint32_t*)(bb + tg * 4);
            uint32_t b01 = *(const uint32_t*)(bb + 16 + tg * 4);
            uint32_t b10 = *(const uint32_t*)(bb + 9216 + tg * 4);
            uint32_t b11 = *(const uint32_t*)(bb + 9216 + 16 + tg * 4);
            mma8(D0[0][ni], afr[0], b00, b01);
            mma8(D0[1][ni], afr[1], b00, b01);
            mma8(D1[0][ni], afr[0], b10, b11);
            mma8(D1[1][ni], afr[1], b10, b11);
        }
    }
}

// ---------------- layer 1 kernel: K=896, NOUT=128, NT=2 in-CTA -------------
__global__ void __launch_bounds__(256, 2) gemm_spike_L1(
    const uint16_t* __restrict__ Min, const int8_t* __restrict__ Wq,
    const float* __restrict__ Sc, const float* __restrict__ bias,
    uint16_t* __restrict__ Mout)
{
    extern __shared__ __align__(16) char sm[];
    constexpr int OFF_A = 14336;          // masks 8*896*2 = 14336, then A 18432
    constexpr int OFF_B = OFF_A + 18432;  // 2 x 18432

    const uint32_t sbase = smem_u32(sm);
    const int tid = threadIdx.x;
    const int lane = tid & 31, wid = tid >> 5;
    const int wm2 = wid >> 1, wn = wid & 1;
    const int g = lane >> 2, tg = lane & 3;
    const int b0 = blockIdx.x * 8;

    {   // stage masks permuted: (m0,m2) | (m1,m3) per u64
        const uint4* msrc = (const uint4*)(Min + (size_t)b0 * KP1);
        uint4* mdst = (uint4*)sm;
        for (int u = tid; u < 896; u += 256) {
            uint4 v = msrc[u];
            uint4 o;
            o.x = __byte_perm(v.x, v.y, 0x5410);
            o.y = __byte_perm(v.x, v.y, 0x7632);
            o.z = __byte_perm(v.z, v.w, 0x5410);
            o.w = __byte_perm(v.z, v.w, 0x7632);
            mdst[u] = o;
        }
    }
    __syncthreads();

    for (int nt = 0; nt < 2; nt++) {
        const int n0 = nt * 64;
        int D0[2][4][4], D1[2][4][4];
#pragma unroll
        for (int mi = 0; mi < 2; mi++)
#pragma unroll
            for (int ni = 0; ni < 4; ni++)
#pragma unroll
                for (int r = 0; r < 4; r++) { D0[mi][ni][r] = 0; D1[mi][ni][r] = 0; }

        auto loadB = [&](int p, int buf) {
            for (int v = tid; v < 1024; v += 256) {
                int l = v >> 9, rem = v & 511, r = rem >> 3, c8 = rem & 7;
                const int8_t* src = Wq + ((size_t)l * 128 + n0 + r) * KP1 + p * 128 + c8 * 16;
                cpa16(sbase + OFF_B + buf * 18432 + l * 9216 + r * 144 + c8 * 16, src, 16u);
            }
            asm volatile("cp.async.commit_group;");
        };
        loadB(0, 0);

#pragma unroll 1
        for (int p = 0; p < 7; p++) {
            const int buf = p & 1;
            if (p < 6) loadB(p + 1, buf ^ 1);
            expand_panel(sm, sm + OFF_A, KP1 / 4, p, tid);
            if (p < 6) asm volatile("cp.async.wait_group 1;");
            else       asm volatile("cp.async.wait_group 0;");
            __syncthreads();
            mma_panel<int>(sm + OFF_A, sm + OFF_B + buf * 18432, wm2, wn, g, tg, D0, D1);
            __syncthreads();
        }

        // combine -> scan buffer (pitch 68 floats), overlays A+B region
        float* cs = (float*)(sm + OFF_A);
#pragma unroll
        for (int mi = 0; mi < 2; mi++)
#pragma unroll
            for (int ni = 0; ni < 4; ni++)
#pragma unroll
                for (int r = 0; r < 4; r++) {
                    int row = wm2 * 32 + mi * 16 + g + (r >> 1) * 8;
                    int col = wn * 32 + ni * 8 + tg * 2 + (r & 1);
                    float s0 = __ldg(Sc + n0 + col);
                    cs[row * 68 + col] = s0 * (float)D0[mi][ni][r] +
                                         s0 * (1.0f / 254.0f) * (float)D1[mi][ni][r];
                }
        __syncthreads();

#pragma unroll
        for (int u = 0; u < 2; u++) {
            int pr = tid + 256 * u;
            int j = pr & 63, bl = pr >> 6;
            int jj = n0 + j;
            float bj = __ldg(bias + jj);
            const float* colp = cs + bl * 16 * 68 + j;
            float v = 0.0f;
            uint32_t msk = 0;
            bool flag = false;
#pragma unroll
            for (int t = 0; t < 16; t++) {
                v = (v + colp[t * 68]) + bj;
                flag |= (fabsf(v - 1.0f) < EPS);
                if (v >= 1.0f) { msk |= (1u << t); v -= 1.0f; }
            }
            int b = b0 + bl;
            Mout[(size_t)b * 128 + jj] = (uint16_t)msk;
            if (flag) {
                int s = atomicAdd(&g_cnt[0], 1);
                if (s < FCAP) g_flag[0][s] = ((uint32_t)b << 10) | (uint32_t)jj;
            }
        }
        __syncthreads();   // scan buffer reused by next tile's expansion
    }
}

// ---------------- K=128 layers: NT N-tiles looped in-CTA -------------------
template <int NT, int NOUT, bool IS_LAST, int LID>
__global__ void __launch_bounds__(256, 2) gemm_spike_K128(
    const uint16_t* __restrict__ Min, const int8_t* __restrict__ Wq,
    const float* __restrict__ Sc, const float* __restrict__ bias,
    uint16_t* __restrict__ Mout, float* __restrict__ Out)
{
    extern __shared__ __align__(16) char sm[];
    constexpr int OFF_A  = 2048;            // masks 8*128*2
    constexpr int OFF_B  = OFF_A + 18432;   // 2 x 18432
    constexpr int OFF_CS = OFF_B + 36864;   // 128 x 68 floats

    const uint32_t sbase = smem_u32(sm);
    const int tid = threadIdx.x;
    const int lane = tid & 31, wid = tid >> 5;
    const int wm2 = wid >> 1, wn = wid & 1;
    const int g = lane >> 2, tg = lane & 3;
    const int b0 = blockIdx.x * 8;

    {   // stage masks permuted
        const uint4* msrc = (const uint4*)(Min + (size_t)b0 * 128);
        uint4* mdst = (uint4*)sm;
        for (int u = tid; u < 128; u += 256) {
            uint4 v = msrc[u];
            uint4 o;
            o.x = __byte_perm(v.x, v.y, 0x5410);
            o.y = __byte_perm(v.x, v.y, 0x7632);
            o.z = __byte_perm(v.z, v.w, 0x5410);
            o.w = __byte_perm(v.z, v.w, 0x7632);
            mdst[u] = o;
        }
    }

    auto loadB = [&](int nt, int buf) {
        const int n0 = nt * 64;
        for (int v = tid; v < 1024; v += 256) {
            int l = v >> 9, rem = v & 511, r = rem >> 3, c8 = rem & 7;
            int row = n0 + r;
            uint32_t ssz = (row < NOUT) ? 16u : 0u;
            int rc = row < NOUT ? row : 0;
            const int8_t* src = Wq + ((size_t)l * NOUT + rc) * 128 + c8 * 16;
            cpa16(sbase + OFF_B + buf * 18432 + l * 9216 + r * 144 + c8 * 16, src, ssz);
        }
        asm volatile("cp.async.commit_group;");
    };
    loadB(0, 0);
    __syncthreads();                        // masks visible
    expand_panel(sm, sm + OFF_A, 32, 0, tid);  // A expanded ONCE
    __syncthreads();

#pragma unroll 1
    for (int nt = 0; nt < NT; nt++) {
        const int buf = nt & 1;
        const int n0 = nt * 64;
        if (nt + 1 < NT) loadB(nt + 1, buf ^ 1);
        if (nt + 1 < NT) asm volatile("cp.async.wait_group 1;");
        else             asm volatile("cp.async.wait_group 0;");
        __syncthreads();                    // B(nt) visible

        int D0[2][4][4], D1[2][4][4];
#pragma unroll
        for (int mi = 0; mi < 2; mi++)
#pragma unroll
            for (int ni = 0; ni < 4; ni++)
#pragma unroll
                for (int r = 0; r < 4; r++) { D0[mi][ni][r] = 0; D1[mi][ni][r] = 0; }

        mma_panel<int>(sm + OFF_A, sm + OFF_B + buf * 18432, wm2, wn, g, tg, D0, D1);

        float* cs = (float*)(sm + OFF_CS);
#pragma unroll
        for (int mi = 0; mi < 2; mi++)
#pragma unroll
            for (int ni = 0; ni < 4; ni++)
#pragma unroll
                for (int r = 0; r < 4; r++) {
                    int row = wm2 * 32 + mi * 16 + g + (r >> 1) * 8;
                    int col = wn * 32 + ni * 8 + tg * 2 + (r & 1);
                    int jg = n0 + col;
                    float s0 = __ldg(Sc + (jg < NOUT ? jg : 0));
                    cs[row * 68 + col] = s0 * (float)D0[mi][ni][r] +
                                         s0 * (1.0f / 254.0f) * (float)D1[mi][ni][r];
                }
        __syncthreads();                    // cs complete

#pragma unroll
        for (int u = 0; u < 2; u++) {
            int pr = tid + 256 * u;
            int j = pr & 63, bl = pr >> 6;
            int jj = n0 + j;
            if (jj < NOUT) {
                float bj = __ldg(bias + jj);
                const float* colp = cs + bl * 16 * 68 + j;
                float v = 0.0f;
                uint32_t msk = 0;
                bool flag = false;
#pragma unroll
                for (int t = 0; t < 16; t++) {
                    v = (v + colp[t * 68]) + bj;
                    flag |= (fabsf(v - 1.0f) < EPS);
                    if (v >= 1.0f) { msk |= (1u << t); v -= 1.0f; }
                }
                int b = b0 + bl;
                if (IS_LAST)
                    Out[(size_t)b * NOUT + jj] = (float)__popc(msk) * 0.0625f;
                else
                    Mout[(size_t)b * NOUT + jj] = (uint16_t)msk;
                if (flag) {
                    int s = atomicAdd(&g_cnt[LID], 1);
                    if (s < FCAP) g_flag[LID][s] = ((uint32_t)b << 10) | (uint32_t)jj;
                }
            }
        }
        // next iteration's cs writes are separated by its post-wait barrier
    }
}

// ---------------- repair: t-parallel, warp = 2 flagged pairs ---------------
template <int KP, int K, int NOUT, bool IS_LAST, int LID>
__global__ void __launch_bounds__(256) repair_kernel(
    const uint16_t* __restrict__ Min, const float* __restrict__ W,
    const float* __restrict__ bias, uint16_t* __restrict__ Mout,
    float* __restrict__ Out)
{
    int n = g_cnt[LID];
    if (n > FCAP) n = FCAP;
    const int lane = threadIdx.x & 31;
    const int grp = lane >> 4, tl = lane & 15;
    const int wglob = (blockIdx.x * blockDim.x + threadIdx.x) >> 5;
    const int nwarps = (gridDim.x * blockDim.x) >> 5;

    for (int s0 = wglob * 2; s0 < n; s0 += nwarps * 2) {
        int s = s0 + grp;
        float acc = 0.0f;
        int b = 0, j = 0;
        bool active = (s < n);
        if (active) {
            uint32_t pk = g_flag[LID][s];
            b = (int)(pk >> 10); j = (int)(pk & 1023u);
            const uint16_t* mrow = Min + (size_t)b * KP;
            const float* wr = W + (size_t)j * K;
            const uint32_t bit = 1u << tl;
            for (int i = 0; i < K; i++) {
                unsigned m = mrow[i];
                if (m & bit) acc += wr[i];
            }
        }
        float bj = active ? bias[j] : 0.0f;
        float v = 0.0f;
        uint32_t msk = 0;
#pragma unroll
        for (int t = 0; t < TSTEPS; t++) {
            float a = __shfl_sync(0xFFFFFFFFu, acc, (lane & 16) + t);
            v = (v + a) + bj;
            if (v >= 1.0f) { msk |= (1u << t); v -= 1.0f; }
        }
        if (active && tl == 0) {
            if (IS_LAST)
                Out[(size_t)b * NOUT + j] = (float)__popc(msk) * 0.0625f;
            else
                Mout[(size_t)b * NOUT + j] = (uint16_t)msk;
        }
    }
}

// ---------------------------------------------------------------------------
extern "C" void kernel_launch(void* const* d_in, const int* in_sizes, int n_in,
                              void* d_out, int out_size)
{
    const float* features = (const float*)d_in[0];
    const float* W1 = (const float*)d_in[1];
    const float* b1 = (const float*)d_in[2];
    const float* W2 = (const float*)d_in[3];
    const float* b2 = (const float*)d_in[4];
    const float* W3 = (const float*)d_in[5];
    const float* b3 = (const float*)d_in[6];
    const float* W4 = (const float*)d_in[7];
    const float* b4 = (const float*)d_in[8];
    float* out = (float*)d_out;

    uint16_t *m0, *m1, *m2, *m3;
    int8_t *q1, *q2, *q3, *q4;
    float *s1, *s2, *s3, *s4;
    cudaGetSymbolAddress((void**)&m0, g_M0);
    cudaGetSymbolAddress((void**)&m1, g_M1);
    cudaGetSymbolAddress((void**)&m2, g_M2);
    cudaGetSymbolAddress((void**)&m3, g_M3);
    cudaGetSymbolAddress((void**)&q1, g_Q1);
    cudaGetSymbolAddress((void**)&q2, g_Q2);
    cudaGetSymbolAddress((void**)&q3, g_Q3);
    cudaGetSymbolAddress((void**)&q4, g_Q4);
    cudaGetSymbolAddress((void**)&s1, g_S1);
    cudaGetSymbolAddress((void**)&s2, g_S2);
    cudaGetSymbolAddress((void**)&s3, g_S3);
    cudaGetSymbolAddress((void**)&s4, g_S4);

    zero_cnt_kernel<<<1, 32>>>();
    enc_kernel<<<(BATCH * KP1 + 255) / 256, 256>>>(features);
    wsplit<<<128, 32>>>(W1, q1, s1, 128, 784, KP1);
    wsplit<<<128, 32>>>(W2, q2, s2, 128, 128, 128);
    wsplit<<<128, 32>>>(W3, q3, s3, 128, 128, 128);
    wsplit<<<784, 32>>>(W4, q4, s4, 784, 128, 128);

    constexpr int SM_L1 = 14336 + 18432 + 2 * 18432;                    // 69632
    constexpr int SM_K  = 2048 + 18432 + 2 * 18432 + 128 * 68 * 4;      // 92160

    cudaFuncSetAttribute(gemm_spike_L1,
                         cudaFuncAttributeMaxDynamicSharedMemorySize, SM_L1);
    cudaFuncSetAttribute(gemm_spike_K128<2, 128, false, 1>,
                         cudaFuncAttributeMaxDynamicSharedMemorySize, SM_K);
    cudaFuncSetAttribute(gemm_spike_K128<2, 128, false, 2>,
                         cudaFuncAttributeMaxDynamicSharedMemorySize, SM_K);
    cudaFuncSetAttribute(gemm_spike_K128<13, 784, true, 3>,
                         cudaFuncAttributeMaxDynamicSharedMemorySize, SM_K);

    gemm_spike_L1<<<BATCH / 8, 256, SM_L1>>>(m0, q1, s1, b1, m1);
    repair_kernel<KP1, 784, 128, false, 0><<<296, 256>>>(m0, W1, b1, m1, nullptr);

    gemm_spike_K128<2, 128, false, 1><<<BATCH / 8, 256, SM_K>>>(m1, q2, s2, b2, m2, nullptr);
    repair_kernel<128, 128, 128, false, 1><<<296, 256>>>(m1, W2, b2, m2, nullptr);

    gemm_spike_K128<2, 128, false, 2><<<BATCH / 8, 256, SM_K>>>(m2, q3, s3, b3, m3, nullptr);
    repair_kernel<128, 128, 128, false, 2><<<296, 256>>>(m2, W3, b3, m3, nullptr);

    gemm_spike_K128<13, 784, true, 3><<<BATCH / 8, 256, SM_K>>>(m3, q4, s4, b4, nullptr, out);
    repair_kernel<128, 128, 784, true, 3><<<296, 256>>>(m3, W4, b4, nullptr, out);
}